// round 1
// baseline (speedup 1.0000x reference)
#include <cuda_runtime.h>
#include <math.h>

#define Hd 64
#define Bn 16
#define Tn 64
#define Kn 32
#define STAGES 4

// Scratch (device globals: no allocation allowed)
__device__ float g_pe[65 * Hd];            // positional encodings pe[0..64][64]
__device__ float g_et[Bn * Tn * Hd];       // et used at step i, per (b,i)
__device__ float g_energy[Bn * Tn * Kn];   // ||gelu(...)|| per (b,i,k)

__device__ __forceinline__ float gelu_f(float x) {
    return 0.5f * x * (1.0f + erff(x * 0.7071067811865476f));
}

// ---------------------------------------------------------------------------
// Kernel 0: positional encoding table.
// ang = p * 10000^(2j/64) computed in f32 (matches jax f32 path), sin/cos via
// libdevice accurate versions (full range reduction, no fast-math).
// ---------------------------------------------------------------------------
__global__ void pe_kernel() {
    int t = blockIdx.x * blockDim.x + threadIdx.x;
    if (t < 65 * 32) {
        int p = t >> 5, j = t & 31;
        float div = powf(10000.0f, (2.0f * (float)j) * (1.0f / 64.0f));
        float ang = (float)p * div;
        g_pe[p * Hd + 2 * j]     = sinf(ang);
        g_pe[p * Hd + 2 * j + 1] = cosf(ang);
    }
}

// ---------------------------------------------------------------------------
// Kernel 1: the serial chain. One block per batch b (16 blocks, 128 threads).
// Per step: k=0 matvec (weights prefetched 4 deep via cp.async), gelu,
// cache update, masked-softmax attention over cache -> next et.
// Stores et[b][i] for the bulk kernel.
// ---------------------------------------------------------------------------
__global__ void __launch_bounds__(128) chain_kernel(
    const int*   __restrict__ neighbor_ids,
    const int*   __restrict__ param_indices,
    const float* __restrict__ weights,
    const float* __restrict__ biases,
    const float* __restrict__ node_bias,
    const float* __restrict__ positions)
{
    extern __shared__ float sm[];
    float* Wst   = sm;                        // STAGES * 4096
    float* bst   = Wst + STAGES * 4096;       // STAGES * 64
    float* cache = bst + STAGES * 64;         // 64 * 64
    float* et_s  = cache + 4096;              // 64
    float* pos_s = et_s + 64;                 // 64
    float* attw  = pos_s + 64;                // 64

    int b = blockIdx.x;
    int tid = threadIdx.x;

    if (tid < 64) {
        pos_s[tid] = positions[tid];          // positions[0, t, 0]
        int nid = neighbor_ids[b * (Tn * Kn * 2)];  // neighbor_ids[b,0,0,0]
        et_s[tid] = gelu_f(1.0f / 64.0f + node_bias[nid * Hd + tid] + g_pe[tid]);
    }

    // Prologue: prefetch k=0 weight matrices for steps 0..STAGES-1
    for (int s = 0; s < STAGES; ++s) {
        int idx = param_indices[(b * Tn + s) * Kn];
        const float4* src = (const float4*)(weights + (size_t)idx * 4096);
        float* dstW = Wst + s * 4096;
        #pragma unroll
        for (int r = 0; r < 8; ++r) {
            unsigned da = (unsigned)__cvta_generic_to_shared(dstW + (tid + r * 128) * 4);
            asm volatile("cp.async.cg.shared.global [%0], [%1], 16;\n"
                         :: "r"(da), "l"(src + tid + r * 128));
        }
        if (tid < 16) {
            unsigned da = (unsigned)__cvta_generic_to_shared(bst + s * 64 + tid * 4);
            asm volatile("cp.async.cg.shared.global [%0], [%1], 16;\n"
                         :: "r"(da), "l"((const float4*)(biases + (size_t)idx * 64) + tid));
        }
        asm volatile("cp.async.commit_group;\n");
    }

    for (int i = 0; i < Tn; ++i) {
        asm volatile("cp.async.wait_group %0;\n" :: "n"(STAGES - 1));
        __syncthreads();

        int st = i & (STAGES - 1);
        if (tid < 64) {
            const float* W = Wst + st * 4096;
            float y = 0.f;
            #pragma unroll
            for (int h = 0; h < 64; ++h) y = fmaf(et_s[h], W[h * 64 + tid], y);
            y += bst[st * 64 + tid] + g_pe[(i + 1) * 64 + tid];
            float g = gelu_f(y);
            g_et[(b * Tn + i) * Hd + tid] = et_s[tid];   // et used at step i
            cache[i * 64 + tid] = g;                      // cache[:, i] = nxt[:, 0]
        }
        __syncthreads();   // stage st fully consumed; cache[i] visible

        // Prefetch step i+STAGES into the stage we just freed
        int pf = i + STAGES;
        if (pf < Tn) {
            int idx = param_indices[(b * Tn + pf) * Kn];
            const float4* src = (const float4*)(weights + (size_t)idx * 4096);
            float* dstW = Wst + st * 4096;
            #pragma unroll
            for (int r = 0; r < 8; ++r) {
                unsigned da = (unsigned)__cvta_generic_to_shared(dstW + (tid + r * 128) * 4);
                asm volatile("cp.async.cg.shared.global [%0], [%1], 16;\n"
                             :: "r"(da), "l"(src + tid + r * 128));
            }
            if (tid < 16) {
                unsigned da = (unsigned)__cvta_generic_to_shared(bst + st * 64 + tid * 4);
                asm volatile("cp.async.cg.shared.global [%0], [%1], 16;\n"
                             :: "r"(da), "l"((const float4*)(biases + (size_t)idx * 64) + tid));
            }
        }
        asm volatile("cp.async.commit_group;\n");  // empty groups in tail keep wait_group count valid

        // Next et: softmax over positions[0..i] applied to cache rows 0..i
        if (i + 1 < Tn) {
            if (tid < 64) {
                float m = -1e30f;
                for (int t = 0; t <= i; ++t) m = fmaxf(m, pos_s[t]);
                float ssum = 0.f;
                for (int t = 0; t <= i; ++t) ssum += expf(pos_s[t] - m);
                if (tid <= i) attw[tid] = expf(pos_s[tid] - m) / ssum;
            }
            __syncthreads();
            if (tid < 64) {
                float e = 0.f;
                for (int t = 0; t <= i; ++t) e = fmaf(attw[t], cache[t * 64 + tid], e);
                et_s[tid] = e;
            }
            // next iteration's leading __syncthreads orders et_s for the matvec
        }
    }
}

// ---------------------------------------------------------------------------
// Kernel 2: bulk energies. One warp per (b, i, k): 32768 warps.
// Fully-coalesced direct LDG of the 16KB weight matrix (each lane handles two
// output columns via float2; per-h the warp reads exactly two 128B lines).
// ---------------------------------------------------------------------------
__global__ void __launch_bounds__(256) bulk_kernel(
    const int*   __restrict__ param_indices,
    const float* __restrict__ weights,
    const float* __restrict__ biases)
{
    __shared__ float ets[8][64];
    int wp   = threadIdx.x >> 5;
    int lane = threadIdx.x & 31;
    int w = blockIdx.x * 8 + wp;        // 0..32767
    int k = w & 31;
    int b = (w >> 5) & 15;
    int i = w >> 9;
    int bt = b * Tn + i;
    int idx = param_indices[bt * Kn + k];

    float2 e2 = *(const float2*)(g_et + bt * Hd + 2 * lane);
    ets[wp][2 * lane]     = e2.x;
    ets[wp][2 * lane + 1] = e2.y;
    __syncwarp();

    const float* Wp = weights + (size_t)idx * 4096 + 2 * lane;
    float y0 = 0.f, y1 = 0.f;
    #pragma unroll 16
    for (int h = 0; h < 64; ++h) {
        float2 wv = *(const float2*)(Wp + h * 64);
        float eh = ets[wp][h];
        y0 = fmaf(eh, wv.x, y0);
        y1 = fmaf(eh, wv.y, y1);
    }
    float2 bv = *(const float2*)(biases + (size_t)idx * 64 + 2 * lane);
    float2 pv = *(const float2*)(g_pe + (i + 1) * 64 + 2 * lane);
    float g0 = gelu_f(y0 + bv.x + pv.x);
    float g1 = gelu_f(y1 + bv.y + pv.y);
    float sq = g0 * g0 + g1 * g1;
    #pragma unroll
    for (int off = 16; off; off >>= 1) sq += __shfl_xor_sync(0xffffffffu, sq, off);
    if (lane == 0) g_energy[bt * Kn + k] = sqrtf(sq);
}

// ---------------------------------------------------------------------------
// Kernel 3: loss = sum over (b,i) of (logsumexp_k(E) - E[k=0]) / (B*T)
// ---------------------------------------------------------------------------
__global__ void __launch_bounds__(1024) loss_kernel(float* out) {
    __shared__ float red[1024];
    int t = threadIdx.x;           // t = b*64 + i
    const float* e = g_energy + t * Kn;
    float m = -1e30f;
    #pragma unroll
    for (int j = 0; j < Kn; ++j) m = fmaxf(m, e[j]);
    float s = 0.f;
    #pragma unroll
    for (int j = 0; j < Kn; ++j) s += expf(e[j] - m);
    float lse = m + logf(s);
    red[t] = lse - e[0];
    __syncthreads();
    #pragma unroll
    for (int off = 512; off; off >>= 1) {
        if (t < off) red[t] += red[t + off];
        __syncthreads();
    }
    if (t == 0) out[0] = red[0] * (1.0f / 1024.0f);
}

extern "C" void kernel_launch(void* const* d_in, const int* in_sizes, int n_in,
                              void* d_out, int out_size) {
    const int*   neighbor_ids  = (const int*)d_in[0];
    const int*   param_indices = (const int*)d_in[1];
    const float* weights       = (const float*)d_in[2];
    const float* biases        = (const float*)d_in[3];
    const float* node_bias     = (const float*)d_in[4];
    const float* positions     = (const float*)d_in[5];
    float* out = (float*)d_out;

    cudaFuncSetAttribute(chain_kernel,
                         cudaFuncAttributeMaxDynamicSharedMemorySize, 86016);

    pe_kernel<<<9, 256>>>();
    chain_kernel<<<Bn, 128, 83712>>>(neighbor_ids, param_indices, weights,
                                     biases, node_bias, positions);
    bulk_kernel<<<4096, 256>>>(param_indices, weights, biases);
    loss_kernel<<<1, 1024>>>(out);
}

// round 2
// speedup vs baseline: 1.1660x; 1.1660x over previous
#include <cuda_runtime.h>
#include <math.h>

#define Hd 64
#define Bn 16
#define Tn 64
#define Kn 32
#define CST 8   // chain prefetch stages

// Scratch (device globals: no allocation allowed)
__device__ float g_pe[65 * Hd];            // positional encodings pe[0..64][64]
__device__ float g_et[Bn * Tn * Hd];       // et used at step i, per (b,i)
__device__ float g_energy[Bn * Tn * Kn];   // ||gelu(...)|| per (b,i,k)

__device__ __forceinline__ float gelu_f(float x) {
    return 0.5f * x * (1.0f + erff(x * 0.7071067811865476f));
}

// ---------------------------------------------------------------------------
// Kernel 0: positional encoding table (accurate sin/cos, matches jax f32 path)
// ---------------------------------------------------------------------------
__global__ void pe_kernel() {
    int t = blockIdx.x * blockDim.x + threadIdx.x;
    if (t < 65 * 32) {
        int p = t >> 5, j = t & 31;
        float div = powf(10000.0f, (2.0f * (float)j) * (1.0f / 64.0f));
        float ang = (float)p * div;
        g_pe[p * Hd + 2 * j]     = sinf(ang);
        g_pe[p * Hd + 2 * j + 1] = cosf(ang);
    }
}

// ---------------------------------------------------------------------------
// Kernel 1: serial chain, O(1) per step via incremental prefix softmax:
//   S_i = S_{i-1} + e^{p_i-m},  A_i = A_{i-1} + e^{p_i-m} * cache_i,
//   et_{i+1} = A_i / S_i    (global max m cancels in the ratio)
// One block per batch (16 blocks, 256 threads). k=0 weights prefetched
// 8 deep via cp.async by all 256 threads; matvec by 64 threads (1 col each,
// conflict-free LDS, 4 accumulators).
// ---------------------------------------------------------------------------
__global__ void __launch_bounds__(256) chain_kernel(
    const int*   __restrict__ neighbor_ids,
    const int*   __restrict__ param_indices,
    const float* __restrict__ weights,
    const float* __restrict__ biases,
    const float* __restrict__ node_bias,
    const float* __restrict__ positions)
{
    extern __shared__ float sm[];
    float* Wst   = sm;                     // CST * 4096
    float* bst   = Wst + CST * 4096;       // CST * 64
    float* et_s  = bst + CST * 64;         // 64
    float* A     = et_s + 64;              // 64
    float* pos_s = A + 64;                 // 64

    int b = blockIdx.x;
    int tid = threadIdx.x;

    // Prologue: start prefetching k=0 weights for steps 0..CST-1 immediately
    for (int s = 0; s < CST; ++s) {
        int idx = __ldg(&param_indices[(b * Tn + s) * Kn]);
        const float4* src = (const float4*)(weights + (size_t)idx * 4096);
        float* dW = Wst + s * 4096;
        #pragma unroll
        for (int r = 0; r < 4; ++r) {
            unsigned da = (unsigned)__cvta_generic_to_shared(dW + (tid + r * 256) * 4);
            asm volatile("cp.async.cg.shared.global [%0], [%1], 16;\n"
                         :: "r"(da), "l"(src + tid + r * 256));
        }
        if (tid < 16) {
            unsigned da = (unsigned)__cvta_generic_to_shared(bst + s * 64 + tid * 4);
            asm volatile("cp.async.cg.shared.global [%0], [%1], 16;\n"
                         :: "r"(da), "l"((const float4*)(biases + (size_t)idx * 64) + tid));
        }
        asm volatile("cp.async.commit_group;\n");
    }

    if (tid < 64) {
        pos_s[tid] = positions[tid];
        int nid = neighbor_ids[b * (Tn * Kn * 2)];
        et_s[tid] = gelu_f(1.0f / 64.0f + node_bias[nid * Hd + tid] + g_pe[tid]);
        A[tid] = 0.0f;
    }
    __syncthreads();

    float mAll = -1e30f;
    #pragma unroll 8
    for (int t = 0; t < Tn; ++t) mAll = fmaxf(mAll, pos_s[t]);

    float S = 0.0f;

    for (int i = 0; i < Tn; ++i) {
        asm volatile("cp.async.wait_group %0;\n" :: "n"(CST - 1));
        __syncthreads();

        int st = i & (CST - 1);
        float g = 0.0f;
        if (tid < 64) {
            g_et[(b * Tn + i) * Hd + tid] = et_s[tid];   // et used at step i
            const float* W = Wst + st * 4096;
            float y0 = 0.f, y1 = 0.f, y2 = 0.f, y3 = 0.f;
            #pragma unroll
            for (int h = 0; h < 64; h += 4) {
                y0 = fmaf(et_s[h    ], W[(h    ) * 64 + tid], y0);
                y1 = fmaf(et_s[h + 1], W[(h + 1) * 64 + tid], y1);
                y2 = fmaf(et_s[h + 2], W[(h + 2) * 64 + tid], y2);
                y3 = fmaf(et_s[h + 3], W[(h + 3) * 64 + tid], y3);
            }
            float y = (y0 + y1) + (y2 + y3);
            y += bst[st * 64 + tid] + g_pe[(i + 1) * 64 + tid];
            g = gelu_f(y);
        }
        float ew = expf(pos_s[i] - mAll);
        S += ew;
        __syncthreads();   // stage st + et_s fully consumed

        if (tid < 64) {
            float a = A[tid] + ew * g;
            A[tid] = a;
            et_s[tid] = a / S;
        }

        // Prefetch step i+CST into freed stage
        int pf = i + CST;
        if (pf < Tn) {
            int idx = __ldg(&param_indices[(b * Tn + pf) * Kn]);
            const float4* src = (const float4*)(weights + (size_t)idx * 4096);
            float* dW = Wst + st * 4096;
            #pragma unroll
            for (int r = 0; r < 4; ++r) {
                unsigned da = (unsigned)__cvta_generic_to_shared(dW + (tid + r * 256) * 4);
                asm volatile("cp.async.cg.shared.global [%0], [%1], 16;\n"
                             :: "r"(da), "l"(src + tid + r * 256));
            }
            if (tid < 16) {
                unsigned da = (unsigned)__cvta_generic_to_shared(bst + st * 64 + tid * 4);
                asm volatile("cp.async.cg.shared.global [%0], [%1], 16;\n"
                             :: "r"(da), "l"((const float4*)(biases + (size_t)idx * 64) + tid));
            }
        }
        asm volatile("cp.async.commit_group;\n");  // empty tail groups keep wait count valid
    }
}

// ---------------------------------------------------------------------------
// Kernel 2: bulk energies. One warp per (b, i, k): 32768 warps, coalesced LDG
// of each 16KB matrix (float2 per lane; 2 full 128B lines per h-row).
// ---------------------------------------------------------------------------
__global__ void __launch_bounds__(256) bulk_kernel(
    const int*   __restrict__ param_indices,
    const float* __restrict__ weights,
    const float* __restrict__ biases)
{
    __shared__ float ets[8][64];
    int wp   = threadIdx.x >> 5;
    int lane = threadIdx.x & 31;
    int w = blockIdx.x * 8 + wp;        // 0..32767
    int k = w & 31;
    int b = (w >> 5) & 15;
    int i = w >> 9;
    int bt = b * Tn + i;
    int idx = param_indices[bt * Kn + k];

    float2 e2 = *(const float2*)(g_et + bt * Hd + 2 * lane);
    ets[wp][2 * lane]     = e2.x;
    ets[wp][2 * lane + 1] = e2.y;
    __syncwarp();

    const float* Wp = weights + (size_t)idx * 4096 + 2 * lane;
    float y0 = 0.f, y1 = 0.f;
    #pragma unroll 16
    for (int h = 0; h < 64; ++h) {
        float2 wv = *(const float2*)(Wp + h * 64);
        float eh = ets[wp][h];
        y0 = fmaf(eh, wv.x, y0);
        y1 = fmaf(eh, wv.y, y1);
    }
    float2 bv = *(const float2*)(biases + (size_t)idx * 64 + 2 * lane);
    float2 pv = *(const float2*)(g_pe + (i + 1) * 64 + 2 * lane);
    float g0 = gelu_f(y0 + bv.x + pv.x);
    float g1 = gelu_f(y1 + bv.y + pv.y);
    float sq = g0 * g0 + g1 * g1;
    #pragma unroll
    for (int off = 16; off; off >>= 1) sq += __shfl_xor_sync(0xffffffffu, sq, off);
    if (lane == 0) g_energy[bt * Kn + k] = sqrtf(sq);
}

// ---------------------------------------------------------------------------
// Kernel 3: loss = mean over (b,i) of (logsumexp_k(E) - E[k=0])
// Fast-math exp/log: error ~1e-7, budget is 1e-3.
// ---------------------------------------------------------------------------
__global__ void __launch_bounds__(1024) loss_kernel(float* out) {
    __shared__ float red[1024];
    int t = threadIdx.x;           // t = b*64 + i
    const float* e = g_energy + t * Kn;
    float m = -1e30f;
    #pragma unroll
    for (int j = 0; j < Kn; ++j) m = fmaxf(m, e[j]);
    float s = 0.f;
    #pragma unroll
    for (int j = 0; j < Kn; ++j) s += __expf(e[j] - m);
    float lse = m + __logf(s);
    red[t] = lse - e[0];
    __syncthreads();
    #pragma unroll
    for (int off = 512; off; off >>= 1) {
        if (t < off) red[t] += red[t + off];
        __syncthreads();
    }
    if (t == 0) out[0] = red[0] * (1.0f / 1024.0f);
}

extern "C" void kernel_launch(void* const* d_in, const int* in_sizes, int n_in,
                              void* d_out, int out_size) {
    const int*   neighbor_ids  = (const int*)d_in[0];
    const int*   param_indices = (const int*)d_in[1];
    const float* weights       = (const float*)d_in[2];
    const float* biases        = (const float*)d_in[3];
    const float* node_bias     = (const float*)d_in[4];
    const float* positions     = (const float*)d_in[5];
    float* out = (float*)d_out;

    cudaFuncSetAttribute(chain_kernel,
                         cudaFuncAttributeMaxDynamicSharedMemorySize, 140000);

    pe_kernel<<<9, 256>>>();
    chain_kernel<<<Bn, 256, (CST * 4096 + CST * 64 + 192) * 4>>>(
        neighbor_ids, param_indices, weights, biases, node_bias, positions);
    bulk_kernel<<<4096, 256>>>(param_indices, weights, biases);
    loss_kernel<<<1, 1024>>>(out);
}